// round 14
// baseline (speedup 1.0000x reference)
#include <cuda_runtime.h>

// out[b,m] = dot(inputs[b,m,:], W[m,:]) + bias[m]
// B=1024, M=2048, I=128 (fp32). Compulsory traffic ~1.083 GB -> HBM-bound.
//
// One warp = fixed m, 8 batches processed as TWO sequential 4-row iterations
// (loop NOT unrolled: keeps only 4 x-row loads live -> regs ~30, occ ~83%,
// while giving each warp a second load burst after its first compute tail).
// One W-row + bias load serves all 8 rows. 32-bit indexing throughout.
// 6-shuffle reduction folds 4 rows at once.

constexpr int B_DIM = 1024;
constexpr int M_DIM = 2048;
constexpr int IV    = 128 / 4;              // 32 float4 per row
constexpr int B_PER_ITER = 4;
constexpr int ITERS = 2;                    // 8 batches per warp total
constexpr int THREADS = 256;                // 8 warps/block
// warps = M_DIM * (B_DIM / (B_PER_ITER*ITERS)) = 2048*128 = 262144
constexpr int GRID = (M_DIM * (B_DIM / (B_PER_ITER * ITERS))) / (THREADS / 32);  // 32768

__global__ __launch_bounds__(THREADS, 8)
void diag_linear_kernel(const float4* __restrict__ x,     // [B*M, 32] float4
                        const float4* __restrict__ w,     // [M, 32] float4
                        const float*  __restrict__ bias,  // [M]
                        float*        __restrict__ out)   // [B*M]
{
    const unsigned lane = threadIdx.x & 31u;
    const unsigned warp_global = blockIdx.x * (THREADS / 32) + (threadIdx.x >> 5);

    const unsigned m    = warp_global & (M_DIM - 1u);   // 8 consecutive m per block
    const unsigned bgrp = warp_global >> 11;            // 0..127
    unsigned b = bgrp * (B_PER_ITER * ITERS);           // first batch row

    // W row (L2-resident) + bias: loaded once for all 8 rows.
    const float4 wv = w[m * IV + lane];
    const float  bv = __ldg(&bias[m]);

    // x index of (b, m) row in float4 units; fits in 32 bits (max 2^26).
    unsigned xi = (b * M_DIM + m) * IV + lane;
    const unsigned xstep = M_DIM * IV;                  // advance one batch

#pragma unroll 1
    for (int it = 0; it < ITERS; it++) {
        // 4 independent DRAM loads (front-batched within the iteration).
        float4 a[B_PER_ITER];
#pragma unroll
        for (int r = 0; r < B_PER_ITER; r++) {
            a[r] = x[xi + (unsigned)r * xstep];
        }

        float s[B_PER_ITER];
#pragma unroll
        for (int r = 0; r < B_PER_ITER; r++) {
            s[r] = fmaf(a[r].x, wv.x,
                   fmaf(a[r].y, wv.y,
                   fmaf(a[r].z, wv.z,
                        a[r].w * wv.w)));
        }

        // 6-shuffle 4-row reduction (row-select tree + butterfly).
        const bool hi16 = (lane & 16u) != 0u;
        float c01 = (hi16 ? s[1] : s[0]) + __shfl_xor_sync(0xffffffffu, hi16 ? s[0] : s[1], 16);
        float c23 = (hi16 ? s[3] : s[2]) + __shfl_xor_sync(0xffffffffu, hi16 ? s[2] : s[3], 16);
        const bool hi8 = (lane & 8u) != 0u;
        float c = (hi8 ? c23 : c01) + __shfl_xor_sync(0xffffffffu, hi8 ? c01 : c23, 8);
        c += __shfl_xor_sync(0xffffffffu, c, 4);
        c += __shfl_xor_sync(0xffffffffu, c, 2);
        c += __shfl_xor_sync(0xffffffffu, c, 1);

        // Lane 0 -> row+0, lane 16 -> row+1, lane 8 -> row+2, lane 24 -> row+3.
        if ((lane & 7u) == 0u) {
            const unsigned r = ((lane >> 4) & 1u) | ((lane >> 2) & 2u);
            out[(b + r) * M_DIM + m] = c + bv;
        }

        b  += B_PER_ITER;
        xi += B_PER_ITER * xstep;
    }
}

extern "C" void kernel_launch(void* const* d_in, const int* in_sizes, int n_in,
                              void* d_out, int out_size)
{
    const float4* x    = (const float4*)d_in[0];  // inputs  [B, M, I]
    const float4* w    = (const float4*)d_in[1];  // Rk_weight [M, I]
    const float*  bias = (const float*)d_in[2];   // bias [M]
    float* out = (float*)d_out;                   // [B, M]

    diag_linear_kernel<<<GRID, THREADS>>>(x, w, bias, out);
}